// round 1
// baseline (speedup 1.0000x reference)
#include <cuda_runtime.h>

#define L 2048
#define NCH 16
#define TI 16
#define TJ 64

// 256 MiB scratch for sparsemax probabilities (lower triangle valid only).
__device__ float g_probs[(size_t)NCH * L * L];

// ---------------------------------------------------------------------------
// Block reduction of (sum, count) across 256 threads (8 warps).
// ---------------------------------------------------------------------------
__device__ __forceinline__ void block_reduce2(float& s, float& c, float* red, int tid) {
#pragma unroll
    for (int o = 16; o > 0; o >>= 1) {
        s += __shfl_down_sync(0xffffffffu, s, o);
        c += __shfl_down_sync(0xffffffffu, c, o);
    }
    int wid = tid >> 5, lane = tid & 31;
    if (lane == 0) { red[wid] = s; red[8 + wid] = c; }
    __syncthreads();
    if (tid == 0) {
        float ts = 0.f, tc = 0.f;
#pragma unroll
        for (int k = 0; k < 8; k++) { ts += red[k]; tc += red[8 + k]; }
        red[16] = ts; red[17] = tc;
    }
    __syncthreads();
    s = red[16];
    c = red[17];
}

// ---------------------------------------------------------------------------
// K1: sparsemax per causal row via Michelot fixed-point iteration.
// One block per (channel, row i). Valid prefix length n = i+1.
// Writes probs only for j <= i (rest of scratch is garbage; K2 predicates).
// ---------------------------------------------------------------------------
__global__ __launch_bounds__(256) void sparsemax_kernel(const float* __restrict__ scores) {
    __shared__ float red[18];
    const int i = blockIdx.x;
    const int c = blockIdx.y;
    const int n = i + 1;
    const int tid = threadIdx.x;
    const float* __restrict__ row = scores + ((size_t)c * L + i) * L;
    float* __restrict__ prow = g_probs + ((size_t)c * L + i) * L;

    float v[8];
    bool alive[8];
    float lsum = 0.f;
#pragma unroll
    for (int k = 0; k < 8; k++) {
        int j = tid + (k << 8);
        bool ok = (j < n);
        float x = ok ? row[j] : 0.f;
        v[k] = x;
        alive[k] = ok;
        lsum += x;  // x is 0 when !ok
    }

    float s = lsum, cdummy = 0.f;
    block_reduce2(s, cdummy, red, tid);
    float tau = (s - 1.0f) / (float)n;
    float cnt = (float)n;

    // Michelot: support shrinks monotonically; terminates when stable.
    for (int iter = 0; iter < 300; iter++) {
        float ls = 0.f, lc = 0.f;
#pragma unroll
        for (int k = 0; k < 8; k++) {
            if (alive[k]) {
                if (v[k] > tau) { ls += v[k]; lc += 1.f; }
                else alive[k] = false;
            }
        }
        block_reduce2(ls, lc, red, tid);
        if (lc == cnt) break;      // no removals -> fixed point, tau unchanged
        cnt = lc;
        tau = (ls - 1.0f) / lc;
    }

#pragma unroll
    for (int k = 0; k < 8; k++) {
        int j = tid + (k << 8);
        if (j < n) prow[j] = alive[k] ? (v[k] - tau) : 0.f;
    }
}

// ---------------------------------------------------------------------------
// K2: grouped 3x3 same-pad conv over the (L,L) prob map + bias + causal mask.
// Block = (64, 4): 64 columns x 4 output channels of one group; tile 16 rows.
// Shared tile (4 in-ch x 18 x 66) loaded with the causal predicate; compute
// slides a 3-row ring-buffer window -> 12 LDS + 36 FMA per output.
// Tiles entirely above the diagonal only write zeros.
// ---------------------------------------------------------------------------
__global__ __launch_bounds__(256) void conv_kernel(const float* __restrict__ weight,
                                                   const float* __restrict__ bias,
                                                   float* __restrict__ out) {
    const int g = blockIdx.z;
    const int i0 = blockIdx.y * TI;
    const int j0 = blockIdx.x * TJ;
    const int tx = threadIdx.x;            // 0..63 column
    const int ty = threadIdx.y;            // 0..3 out-ch within group
    const int co = (g << 2) + ty;

    if (j0 > i0 + TI - 1) {
        // fully masked tile: just zero-fill
        float* o = out + (size_t)co * L * L + (size_t)i0 * L + j0 + tx;
#pragma unroll
        for (int ii = 0; ii < TI; ii++) o[(size_t)ii * L] = 0.f;
        return;
    }

    __shared__ float sm[4][TI + 2][TJ + 2];

    // cooperative load with causal/bounds predicate
    const int tid = ty * 64 + tx;
    const int TOT = 4 * (TI + 2) * (TJ + 2);
    for (int idx = tid; idx < TOT; idx += 256) {
        int ch = idx / ((TI + 2) * (TJ + 2));
        int rem = idx % ((TI + 2) * (TJ + 2));
        int ii = rem / (TJ + 2);
        int jj = rem % (TJ + 2);
        int r = i0 + ii - 1;
        int cc = j0 + jj - 1;
        float val = 0.f;
        if (r >= 0 && r < L && cc >= 0 && cc <= r)
            val = g_probs[((size_t)((g << 2) + ch) * L + r) * L + cc];
        sm[ch][ii][jj] = val;
    }
    __syncthreads();

    // weights for this output channel into registers
    float w[4][3][3];
#pragma unroll
    for (int ci = 0; ci < 4; ci++)
#pragma unroll
        for (int kh = 0; kh < 3; kh++)
#pragma unroll
            for (int kw = 0; kw < 3; kw++)
                w[ci][kh][kw] = __ldg(&weight[(((co << 2) + ci) * 3 + kh) * 3 + kw]);
    const float b = __ldg(&bias[co]);

    // ring-buffer window: position of sm row r is r % 3
    float win[4][3][3];
#pragma unroll
    for (int ci = 0; ci < 4; ci++)
#pragma unroll
        for (int kw = 0; kw < 3; kw++) {
            win[ci][0][kw] = sm[ci][0][tx + kw];
            win[ci][1][kw] = sm[ci][1][tx + kw];
        }

    float* obase = out + (size_t)co * L * L;
#pragma unroll
    for (int ii = 0; ii < TI; ii++) {
        const int pnew = (ii + 2) % 3;
#pragma unroll
        for (int ci = 0; ci < 4; ci++)
#pragma unroll
            for (int kw = 0; kw < 3; kw++)
                win[ci][pnew][kw] = sm[ci][ii + 2][tx + kw];

        float acc = b;
#pragma unroll
        for (int ci = 0; ci < 4; ci++)
#pragma unroll
            for (int kh = 0; kh < 3; kh++) {
                const int p = (ii + kh) % 3;
#pragma unroll
                for (int kw = 0; kw < 3; kw++)
                    acc = fmaf(win[ci][p][kw], w[ci][kh][kw], acc);
            }

        const int gi = i0 + ii;
        const int gj = j0 + tx;
        obase[(size_t)gi * L + gj] = (gj <= gi) ? acc : 0.f;
    }
}

extern "C" void kernel_launch(void* const* d_in, const int* in_sizes, int n_in,
                              void* d_out, int out_size) {
    const float* scores = (const float*)d_in[0];
    const float* weight = (const float*)d_in[1];
    const float* bias = (const float*)d_in[2];
    float* out = (float*)d_out;

    dim3 g1(L, NCH);
    sparsemax_kernel<<<g1, 256>>>(scores);

    dim3 g2(L / TJ, L / TI, 4);
    dim3 b2(64, 4);
    conv_kernel<<<g2, b2>>>(weight, bias, out);
}

// round 3
// speedup vs baseline: 1.8253x; 1.8253x over previous
#include <cuda_runtime.h>
#include <cstdint>

#define L 2048
#define NCH 16
#define TI 8
#define TJ 128
#define CAP 1024

// 256 MiB scratch for sparsemax probabilities (lower triangle valid only).
__device__ float g_probs[(size_t)NCH * L * L];

// ---------------------------------------------------------------------------
// packed f32x2 helpers
// ---------------------------------------------------------------------------
__device__ __forceinline__ unsigned long long pk2(float lo, float hi) {
    unsigned long long r;
    asm("mov.b64 %0, {%1, %2};" : "=l"(r) : "f"(lo), "f"(hi));
    return r;
}
__device__ __forceinline__ void upk2(unsigned long long v, float& lo, float& hi) {
    asm("mov.b64 {%0, %1}, %2;" : "=f"(lo), "=f"(hi) : "l"(v));
}
__device__ __forceinline__ unsigned long long fma2(unsigned long long a,
                                                   unsigned long long b,
                                                   unsigned long long c) {
    unsigned long long d;
    asm("fma.rn.f32x2 %0, %1, %2, %3;" : "=l"(d) : "l"(a), "l"(b), "l"(c));
    return d;
}

// ---------------------------------------------------------------------------
// K1: sparsemax per causal row.
//   Property: tau_final >= rowmax - 1  (max prob <= 1). For Gaussian rows only
//   ~22/2048 elements exceed rowmax-1, so compact those into shared and run
//   Michelot with a single warp (no block barriers per iteration).
// ---------------------------------------------------------------------------
__global__ __launch_bounds__(256) void sparsemax_kernel(const float* __restrict__ scores) {
    __shared__ float cand[CAP];
    __shared__ float wmax[8];
    __shared__ int wcnti[8];
    __shared__ float s_tau;
    __shared__ float red[18];

    const int i = blockIdx.x;
    const int c = blockIdx.y;
    const int n = i + 1;
    const int tid = threadIdx.x;
    const int wid = tid >> 5, lane = tid & 31;
    const unsigned FULL = 0xffffffffu;
    const float* __restrict__ row = scores + ((size_t)c * L + i) * L;
    float* __restrict__ prow = g_probs + ((size_t)c * L + i) * L;

    float v[8];
    bool valid[8];
    float m = -3.0e38f;
#pragma unroll
    for (int k = 0; k < 8; k++) {
        int j = tid + (k << 8);
        bool ok = (j < n);
        float x = ok ? row[j] : -3.0e38f;
        v[k] = x;
        valid[k] = ok;
        m = fmaxf(m, x);
    }
#pragma unroll
    for (int o = 16; o > 0; o >>= 1) m = fmaxf(m, __shfl_xor_sync(FULL, m, o));
    if (lane == 0) wmax[wid] = m;
    __syncthreads();
    float mx = wmax[0];
#pragma unroll
    for (int w = 1; w < 8; w++) mx = fmaxf(mx, wmax[w]);
    const float thr = mx - 1.0f;

    // candidate masks (per 256-element slab of this warp)
    unsigned masks[8];
    int wtot = 0;
#pragma unroll
    for (int k = 0; k < 8; k++) {
        bool pred = valid[k] && (v[k] > thr);
        masks[k] = __ballot_sync(FULL, pred);
        wtot += __popc(masks[k]);
    }
    if (lane == 0) wcnti[wid] = wtot;
    __syncthreads();
    int base = 0, total = 0;
#pragma unroll
    for (int w = 0; w < 8; w++) {
        int cw = wcnti[w];
        if (w < wid) base += cw;
        total += cw;
    }

    float tau;
    if (total <= CAP) {
        // deterministic compaction: warp-order, then slab-order, then lane-order
        int pos = base;
        unsigned lmask_lt = (1u << lane) - 1u;
#pragma unroll
        for (int k = 0; k < 8; k++) {
            unsigned mk = masks[k];
            if (mk & (1u << lane)) cand[pos + __popc(mk & lmask_lt)] = v[k];
            pos += __popc(mk);
        }
        __syncthreads();

        if (wid == 0) {
            float t = -3.0e38f;
            int prev = -1;
            for (int iter = 0; iter < 64; iter++) {
                float ls = 0.f;
                int lc = 0;
                for (int q = lane; q < total; q += 32) {
                    float x = cand[q];
                    if (x > t) { ls += x; lc++; }
                }
#pragma unroll
                for (int o = 16; o > 0; o >>= 1) {
                    ls += __shfl_xor_sync(FULL, ls, o);
                    lc += __shfl_xor_sync(FULL, lc, o);
                }
                if (lc == prev) break;
                prev = lc;
                t = (ls - 1.0f) / (float)lc;
            }
            if (lane == 0) s_tau = t;
        }
        __syncthreads();
        tau = s_tau;
    } else {
        // fallback: block-wide Michelot (never triggered for this data)
        bool alive[8];
        float lsum = 0.f;
#pragma unroll
        for (int k = 0; k < 8; k++) {
            alive[k] = valid[k];
            lsum += valid[k] ? v[k] : 0.f;
        }
#pragma unroll
        for (int o = 16; o > 0; o >>= 1) lsum += __shfl_down_sync(FULL, lsum, o);
        if (lane == 0) red[wid] = lsum;
        __syncthreads();
        if (tid == 0) {
            float ts = 0.f;
#pragma unroll
            for (int k = 0; k < 8; k++) ts += red[k];
            red[16] = ts;
        }
        __syncthreads();
        tau = (red[16] - 1.0f) / (float)n;
        float cnt = (float)n;
        for (int iter = 0; iter < 300; iter++) {
            float ls = 0.f, lc = 0.f;
#pragma unroll
            for (int k = 0; k < 8; k++) {
                if (alive[k]) {
                    if (v[k] > tau) { ls += v[k]; lc += 1.f; }
                    else alive[k] = false;
                }
            }
#pragma unroll
            for (int o = 16; o > 0; o >>= 1) {
                ls += __shfl_down_sync(FULL, ls, o);
                lc += __shfl_down_sync(FULL, lc, o);
            }
            if (lane == 0) { red[wid] = ls; red[8 + wid] = lc; }
            __syncthreads();
            if (tid == 0) {
                float ts = 0.f, tc = 0.f;
#pragma unroll
                for (int k = 0; k < 8; k++) { ts += red[k]; tc += red[8 + k]; }
                red[16] = ts; red[17] = tc;
            }
            __syncthreads();
            float gs = red[16], gc = red[17];
            if (gc == cnt) break;
            cnt = gc;
            tau = (gs - 1.0f) / gc;
            __syncthreads();
        }
    }

#pragma unroll
    for (int k = 0; k < 8; k++) {
        int j = tid + (k << 8);
        if (j < n) prow[j] = fmaxf(v[k] - tau, 0.0f);
    }
}

// ---------------------------------------------------------------------------
// K2: grouped 3x3 conv + bias + causal mask, packed f32x2.
//  Block (64,4): tx -> 2 adjacent columns, ty -> out channel of group.
//  Tile: 8 rows x 128 cols. Each thread keeps 8 f32x2 accumulators; every
//  input row is read from shared exactly once per ci (2x LDS.64).
// ---------------------------------------------------------------------------
__global__ __launch_bounds__(256) void conv_kernel(const float* __restrict__ weight,
                                                   const float* __restrict__ bias,
                                                   float* __restrict__ out) {
    const int g = blockIdx.z;
    const int i0 = blockIdx.y * TI;
    const int j0 = blockIdx.x * TJ;
    const int tx = threadIdx.x;     // 0..63
    const int ty = threadIdx.y;     // 0..3
    const int co = (g << 2) + ty;

    if (j0 > i0 + TI - 1) {
        // fully masked tile: vector zero-fill
        float4* o = (float4*)(out + (size_t)co * L * L + (size_t)i0 * L + j0);
        const float4 z4 = make_float4(0.f, 0.f, 0.f, 0.f);
#pragma unroll
        for (int s = 0; s < 4; s++) {
            int idx = tx + (s << 6);          // 0..255
            int r = idx >> 5, c4 = idx & 31;  // 8 rows x 32 float4
            o[(size_t)r * (L / 4) + c4] = z4;
        }
        return;
    }

    __shared__ __align__(16) float sm[4][TI + 2][TJ + 2];

    // cooperative load with causal/bounds predicate (coalesced along jj)
    const int tid = ty * 64 + tx;
    const int TOT = 4 * (TI + 2) * (TJ + 2);       // 5200
    for (int idx = tid; idx < TOT; idx += 256) {
        int ch = idx / ((TI + 2) * (TJ + 2));
        int rem = idx - ch * ((TI + 2) * (TJ + 2));
        int ii = rem / (TJ + 2);
        int jj = rem - ii * (TJ + 2);
        int r = i0 + ii - 1;
        int cc = j0 + jj - 1;
        float val = 0.f;
        if (r >= 0 && r < L && cc >= 0 && cc <= r)
            val = g_probs[((size_t)((g << 2) + ch) * L + r) * L + cc];
        sm[ch][ii][jj] = val;
    }
    __syncthreads();

    const float b = __ldg(&bias[co]);
    unsigned long long acc[TI];
#pragma unroll
    for (int o = 0; o < TI; o++) acc[o] = pk2(b, b);

    const int colb = tx << 1;  // shared col of (j-1)

#pragma unroll 1
    for (int ci = 0; ci < 4; ci++) {
        unsigned long long w2[3][3];
        const float* wp = weight + (((size_t)co * 4 + ci) * 9);
#pragma unroll
        for (int kh = 0; kh < 3; kh++)
#pragma unroll
            for (int kw = 0; kw < 3; kw++) {
                float w = __ldg(&wp[kh * 3 + kw]);
                w2[kh][kw] = pk2(w, w);
            }

#pragma unroll
        for (int r = 0; r < TI + 2; r++) {
            unsigned long long a = *(const unsigned long long*)&sm[ci][r][colb];
            unsigned long long bb = *(const unsigned long long*)&sm[ci][r][colb + 2];
            unsigned long long mid = (a >> 32) | (bb << 32);
            // input row r feeds outputs o = r-kh for kh in {0,1,2}
            if (r <= TI - 1) {
                acc[r] = fma2(a, w2[0][0], acc[r]);
                acc[r] = fma2(mid, w2[0][1], acc[r]);
                acc[r] = fma2(bb, w2[0][2], acc[r]);
            }
            if (r >= 1 && r <= TI) {
                acc[r - 1] = fma2(a, w2[1][0], acc[r - 1]);
                acc[r - 1] = fma2(mid, w2[1][1], acc[r - 1]);
                acc[r - 1] = fma2(bb, w2[1][2], acc[r - 1]);
            }
            if (r >= 2) {
                acc[r - 2] = fma2(a, w2[2][0], acc[r - 2]);
                acc[r - 2] = fma2(mid, w2[2][1], acc[r - 2]);
                acc[r - 2] = fma2(bb, w2[2][2], acc[r - 2]);
            }
        }
    }

    float* obase = out + (size_t)co * L * L;
    const int gj = j0 + (tx << 1);
#pragma unroll
    for (int o = 0; o < TI; o++) {
        const int gi = i0 + o;
        float lo, hi;
        upk2(acc[o], lo, hi);
        float2 st;
        st.x = (gj <= gi) ? lo : 0.f;
        st.y = (gj + 1 <= gi) ? hi : 0.f;
        *(float2*)&obase[(size_t)gi * L + gj] = st;
    }
}

extern "C" void kernel_launch(void* const* d_in, const int* in_sizes, int n_in,
                              void* d_out, int out_size) {
    const float* scores = (const float*)d_in[0];
    const float* weight = (const float*)d_in[1];
    const float* bias = (const float*)d_in[2];
    float* out = (float*)d_out;

    dim3 g1(L, NCH);
    sparsemax_kernel<<<g1, 256>>>(scores);

    dim3 g2(L / TJ, L / TI, 4);
    dim3 b2(64, 4);
    conv_kernel<<<g2, b2>>>(weight, bias, out);
}